// round 9
// baseline (speedup 1.0000x reference)
#include <cuda_runtime.h>
#include <cuda_fp16.h>
#include <cstdint>
#include <cstddef>

#define D 128
#define TILE_ROWS 128
#define GEMM_THREADS 512   // 16 warps: wm = wid&3 (32-row quarter), wn = wid>>2 (64-col group)

#define NUM_USERS_MAX 100000
#define NUM_ITEMS_MAX 50000
#define NUM_EDGES_MAX 600000

// Scratch (allocation-free rule: device globals). Messages stored fp16.
__device__ __half g_U2I[NUM_USERS_MAX * 128];
__device__ __half g_I2U[NUM_ITEMS_MAX * 128];

// CSR scratch
__device__ int g_cnt_i[NUM_ITEMS_MAX];
__device__ int g_cnt_u[NUM_USERS_MAX];
__device__ int g_off_i[NUM_ITEMS_MAX];
__device__ int g_off_u[NUM_USERS_MAX];
__device__ int g_cur_i[NUM_ITEMS_MAX];
__device__ int g_cur_u[NUM_USERS_MAX];
__device__ int g_src_i[NUM_EDGES_MAX];
__device__ int g_src_u[NUM_EDGES_MAX];
__device__ int g_tot_i;
__device__ int g_tot_u;

__device__ __forceinline__ uint32_t smem_u32(const void* p) {
    uint32_t a;
    asm("{ .reg .u64 t; cvta.to.shared.u64 t, %1; cvt.u32.u64 %0, t; }" : "=r"(a) : "l"(p));
    return a;
}

__device__ __forceinline__ void mma_f16(float* c, uint32_t a0, uint32_t a1, uint32_t a2,
                                        uint32_t a3, uint32_t b0, uint32_t b1) {
    asm volatile(
        "mma.sync.aligned.m16n8k16.row.col.f32.f16.f16.f32 "
        "{%0,%1,%2,%3}, {%4,%5,%6,%7}, {%8,%9}, {%0,%1,%2,%3};"
        : "+f"(c[0]), "+f"(c[1]), "+f"(c[2]), "+f"(c[3])
        : "r"(a0), "r"(a1), "r"(a2), "r"(a3), "r"(b0), "r"(b1));
}

// smem layout (fp16 pipeline):
//   Wfrag: 8 ksteps(k16) x 32 n8-tiles x 32 lanes x uint2 = 65536 B
//          (m16n8k16 B fragment: h0=W[o][k0+2t], h1=W[o][k0+2t+1],
//           h2=W[o][k0+2t+8], h3=W[o][k0+2t+9]; o = nt*8 + g)
//   Xs: 128 rows x 136 halves (272 B row stride -> conflict-free LDSM) at 65536
#define XS_LDH  136
#define XS_OFF_U2 8192           // uint2 index of Xs within smem_u2
#define SMEM_BYTES (65536 + TILE_ROWS * XS_LDH * 2)   // 100352

extern __shared__ __align__(16) uint2 smem_u2[];

// Unified persistent GEMM: blocks [0, split) -> user matrices, rest -> item.
__global__ __launch_bounds__(GEMM_THREADS, 1)
void gemm_mma(const float* __restrict__ Xu, int nu,
              const float* __restrict__ Wau, const float* __restrict__ bau,
              const float* __restrict__ Wbu,
              float* __restrict__ Yu, __half* __restrict__ Mu,
              const float* __restrict__ Xi, int ni,
              const float* __restrict__ Wai, const float* __restrict__ bai,
              const float* __restrict__ Wbi,
              float* __restrict__ Yi, __half* __restrict__ Mi,
              int split)
{
    uint2*  Wfrag = smem_u2;
    __half* Xs    = (__half*)(smem_u2 + XS_OFF_U2);
    const uint32_t xs_base = smem_u32(Xs);

    const int tid  = threadIdx.x;
    const int lane = tid & 31;
    const int wid  = tid >> 5;
    const int wm   = wid & 3;        // 32-row quarter of the 128-row tile
    const int wn   = wid >> 2;       // 0..3: 64-col group within 256 outs
    const int g    = lane >> 2;
    const int t    = lane & 3;

    // Per-block work selection
    const float *X, *Wa, *ba, *Wb;
    float* Yself;
    __half* Ymsg;
    int nrows, bidx, nblk;
    if (blockIdx.x < split) {
        X = Xu; Wa = Wau; ba = bau; Wb = Wbu; Yself = Yu; Ymsg = Mu;
        nrows = nu; bidx = blockIdx.x; nblk = split;
    } else {
        X = Xi; Wa = Wai; ba = bai; Wb = Wbi; Yself = Yi; Ymsg = Mi;
        nrows = ni; bidx = blockIdx.x - split; nblk = gridDim.x - split;
    }

    // Build W fragments once (fp16, m16n8k16 fragment-native layout)
    for (int i = tid; i < 8 * 32 * 32; i += GEMM_THREADS) {
        const int l  = i & 31;
        const int nt = (i >> 5) & 31;
        const int ks = i >> 10;                 // 0..7
        const int o  = nt * 8 + (l >> 2);
        const int k  = ks * 16 + (l & 3) * 2;
        const float* Wsrc = (o < 128) ? (Wa + (size_t)o * 128) : (Wb + (size_t)(o - 128) * 128);
        const __half2 lo = __floats2half2_rn(Wsrc[k],     Wsrc[k + 1]);
        const __half2 hi = __floats2half2_rn(Wsrc[k + 8], Wsrc[k + 9]);
        uint2 v;
        v.x = *(const uint32_t*)&lo;
        v.y = *(const uint32_t*)&hi;
        Wfrag[i] = v;
    }

    float2 bias2[8];
    if (wn < 2) {
        #pragma unroll
        for (int nt = 0; nt < 8; nt++) {
            const int col = wn * 64 + nt * 8 + t * 2;
            bias2[nt] = make_float2(ba[col], ba[col + 1]);
        }
    }

    // ldmatrix per-lane source row/col within the 16x16 A tile
    const int lm_row = (lane & 7) + ((lane >> 3) & 1) * 8;  // m offset
    const int lm_col = (lane >> 4) * 8;                     // k offset

    const int ntiles = (nrows + TILE_ROWS - 1) / TILE_ROWS;

    for (int tile = bidx; tile < ntiles; tile += nblk) {
        const int row0 = tile * TILE_ROWS;
        __syncthreads();

        // Stage X tile as fp16 (zero-pad tail rows)
        for (int i = tid; i < TILE_ROWS * 32; i += GEMM_THREADS) {
            const int r = i >> 5, q = i & 31;
            uint2 hv = make_uint2(0u, 0u);
            if (row0 + r < nrows) {
                const float4 v = *(const float4*)&X[(size_t)(row0 + r) * D + q * 4];
                const __half2 h01 = __floats2half2_rn(v.x, v.y);
                const __half2 h23 = __floats2half2_rn(v.z, v.w);
                hv.x = *(const uint32_t*)&h01;
                hv.y = *(const uint32_t*)&h23;
            }
            *(uint2*)&Xs[r * XS_LDH + q * 4] = hv;
        }
        __syncthreads();

        float acc[2][8][4];
        #pragma unroll
        for (int mt = 0; mt < 2; mt++)
            #pragma unroll
            for (int nt = 0; nt < 8; nt++)
                #pragma unroll
                for (int j = 0; j < 4; j++) acc[mt][nt][j] = 0.f;

        #pragma unroll
        for (int ks = 0; ks < 8; ks++) {
            const int k0 = ks * 16;
            uint32_t a[2][4];
            #pragma unroll
            for (int mt = 0; mt < 2; mt++) {
                const int row = wm * 32 + mt * 16 + lm_row;
                const uint32_t addr = xs_base + (uint32_t)(row * XS_LDH + k0 + lm_col) * 2u;
                asm volatile(
                    "ldmatrix.sync.aligned.m8n8.x4.shared.b16 {%0,%1,%2,%3}, [%4];"
                    : "=r"(a[mt][0]), "=r"(a[mt][1]), "=r"(a[mt][2]), "=r"(a[mt][3])
                    : "r"(addr));
            }
            #pragma unroll
            for (int nt = 0; nt < 8; nt++) {
                const uint2 b = Wfrag[(size_t)(ks * 32 + wn * 8 + nt) * 32 + lane];
                mma_f16(acc[0][nt], a[0][0], a[0][1], a[0][2], a[0][3], b.x, b.y);
                mma_f16(acc[1][nt], a[1][0], a[1][1], a[1][2], a[1][3], b.x, b.y);
            }
        }

        #pragma unroll
        for (int mt = 0; mt < 2; mt++) {
            const int r0 = row0 + wm * 32 + mt * 16 + g;
            const int r1 = r0 + 8;
            #pragma unroll
            for (int nt = 0; nt < 8; nt++) {
                const int colg = wn * 64 + nt * 8 + t * 2;
                if (wn < 2) {
                    if (r0 < nrows)
                        *(float2*)&Yself[(size_t)r0 * D + colg] =
                            make_float2(acc[mt][nt][0] + bias2[nt].x,
                                        acc[mt][nt][1] + bias2[nt].y);
                    if (r1 < nrows)
                        *(float2*)&Yself[(size_t)r1 * D + colg] =
                            make_float2(acc[mt][nt][2] + bias2[nt].x,
                                        acc[mt][nt][3] + bias2[nt].y);
                } else {
                    const int colm = colg - 128;
                    if (r0 < nrows)
                        *(__half2*)&Ymsg[(size_t)r0 * D + colm] =
                            __floats2half2_rn(acc[mt][nt][0], acc[mt][nt][1]);
                    if (r1 < nrows)
                        *(__half2*)&Ymsg[(size_t)r1 * D + colm] =
                            __floats2half2_rn(acc[mt][nt][2], acc[mt][nt][3]);
                }
            }
        }
    }
}

// ============================ CSR build ============================
__global__ void zero_k(int nI, int nU) {
    const int i = blockIdx.x * blockDim.x + threadIdx.x;
    if (i < nI) g_cnt_i[i] = 0;
    if (i < nU) g_cnt_u[i] = 0;
    if (i == 0) { g_tot_i = 0; g_tot_u = 0; }
}

__global__ void count_k(const int* __restrict__ eu, const int* __restrict__ ei, int E) {
    const int e = blockIdx.x * blockDim.x + threadIdx.x;
    if (e < E) {
        atomicAdd(&g_cnt_i[__ldg(&ei[e])], 1);
        atomicAdd(&g_cnt_u[__ldg(&eu[e])], 1);
    }
}

// Chip-wide segment allocator: block prefix + ONE atomicAdd per block.
__global__ void alloc_k(const int* __restrict__ cnt, int* __restrict__ off,
                        int* __restrict__ cur, int n, int* __restrict__ total)
{
    __shared__ int wtot[32];
    __shared__ int blk_base;
    const int i = blockIdx.x * blockDim.x + threadIdx.x;
    const int lane = threadIdx.x & 31;
    const int wid = threadIdx.x >> 5;
    const int nw = blockDim.x >> 5;

    const int v = (i < n) ? cnt[i] : 0;

    int p = v;
    #pragma unroll
    for (int d = 1; d < 32; d <<= 1) {
        int t = __shfl_up_sync(0xFFFFFFFFu, p, d);
        if (lane >= d) p += t;
    }
    const int warp_excl = p - v;
    if (lane == 31) wtot[wid] = p;
    __syncthreads();

    if (wid == 0) {
        int wv = (lane < nw) ? wtot[lane] : 0;
        int q = wv;
        #pragma unroll
        for (int d = 1; d < 32; d <<= 1) {
            int t = __shfl_up_sync(0xFFFFFFFFu, q, d);
            if (lane >= d) q += t;
        }
        wtot[lane] = q - wv;
        if (lane == nw - 1) blk_base = atomicAdd(total, q);
    }
    __syncthreads();

    if (i < n) {
        const int o = blk_base + wtot[wid] + warp_excl;
        off[i] = o;
        cur[i] = o;
    }
}

__global__ void fill_k(const int* __restrict__ eu, const int* __restrict__ ei, int E) {
    const int e = blockIdx.x * blockDim.x + threadIdx.x;
    if (e < E) {
        const int u  = __ldg(&eu[e]);
        const int it = __ldg(&ei[e]);
        const int p = atomicAdd(&g_cur_i[it], 1);
        g_src_i[p] = u;
        const int q = atomicAdd(&g_cur_u[u], 1);
        g_src_u[q] = it;
    }
}

// ============================ Gather (fp16 messages) ============================
__device__ __forceinline__ void acc_half4(float4& acc, uint2 raw) {
    const __half2 h0 = *(__half2*)&raw.x;
    const __half2 h1 = *(__half2*)&raw.y;
    const float2 f0 = __half22float2(h0);
    const float2 f1 = __half22float2(h1);
    acc.x += f0.x; acc.y += f0.y; acc.z += f1.x; acc.w += f1.y;
}

__global__ void gather_k(const int* __restrict__ off, const int* __restrict__ cnt,
                         const int* __restrict__ src, const __half* __restrict__ msgs,
                         const float* __restrict__ bias, float* __restrict__ out, int n)
{
    const int node = (blockIdx.x * blockDim.x + threadIdx.x) >> 5;
    if (node >= n) return;
    const int lane = threadIdx.x & 31;
    const int offc = lane * 4;
    const int base = __ldg(&off[node]);
    const int deg  = __ldg(&cnt[node]);

    float4 acc = make_float4(0.f, 0.f, 0.f, 0.f);
    int j = 0;
    for (; j + 4 <= deg; j += 4) {
        const int s0 = __ldg(&src[base + j]);
        const int s1 = __ldg(&src[base + j + 1]);
        const int s2 = __ldg(&src[base + j + 2]);
        const int s3 = __ldg(&src[base + j + 3]);
        const uint2 r0 = *(const uint2*)&msgs[(size_t)s0 * D + offc];
        const uint2 r1 = *(const uint2*)&msgs[(size_t)s1 * D + offc];
        const uint2 r2 = *(const uint2*)&msgs[(size_t)s2 * D + offc];
        const uint2 r3 = *(const uint2*)&msgs[(size_t)s3 * D + offc];
        acc_half4(acc, r0); acc_half4(acc, r1);
        acc_half4(acc, r2); acc_half4(acc, r3);
    }
    for (; j < deg; j++) {
        const int s = __ldg(&src[base + j]);
        acc_half4(acc, *(const uint2*)&msgs[(size_t)s * D + offc]);
    }

    const float fd = (float)deg;
    const float4 b = *(const float4*)&bias[offc];
    float4* po = (float4*)&out[(size_t)node * D + offc];
    float4 o = *po;
    o.x += acc.x + fd * b.x;
    o.y += acc.y + fd * b.y;
    o.z += acc.z + fd * b.z;
    o.w += acc.w + fd * b.w;
    *po = o;
}

// ============================ Host ============================
struct Ctx {
    cudaStream_t s1, s2;
    cudaEvent_t evFork, evCSR, evG, evS2;
    Ctx() {
        cudaStreamCreateWithFlags(&s1, cudaStreamNonBlocking);
        cudaStreamCreateWithFlags(&s2, cudaStreamNonBlocking);
        cudaEventCreateWithFlags(&evFork, cudaEventDisableTiming);
        cudaEventCreateWithFlags(&evCSR,  cudaEventDisableTiming);
        cudaEventCreateWithFlags(&evG,    cudaEventDisableTiming);
        cudaEventCreateWithFlags(&evS2,   cudaEventDisableTiming);
    }
};

extern "C" void kernel_launch(void* const* d_in, const int* in_sizes, int n_in,
                              void* d_out, int out_size)
{
    const float* user_feat = (const float*)d_in[0];
    const float* item_feat = (const float*)d_in[1];
    const int*   edges     = (const int*)d_in[2];
    const float* W_user = (const float*)d_in[3];
    const float* b_user = (const float*)d_in[4];
    const float* W_item = (const float*)d_in[5];
    const float* b_item = (const float*)d_in[6];
    const float* W_u2i  = (const float*)d_in[7];
    const float* b_u2i  = (const float*)d_in[8];
    const float* W_i2u  = (const float*)d_in[9];
    const float* b_i2u  = (const float*)d_in[10];

    const int nU = in_sizes[0] / D;
    const int nI = in_sizes[1] / D;
    const int E  = in_sizes[2] / 2;

    float* user_out = (float*)d_out;
    float* item_out = (float*)d_out + (size_t)nU * D;

    __half *u2i_ptr, *i2u_ptr;
    cudaGetSymbolAddress((void**)&u2i_ptr, g_U2I);
    cudaGetSymbolAddress((void**)&i2u_ptr, g_I2U);
    int *cnt_i, *cnt_u, *off_i, *off_u, *src_i, *src_u, *cur_i, *cur_u, *tot_i, *tot_u;
    cudaGetSymbolAddress((void**)&cnt_i, g_cnt_i);
    cudaGetSymbolAddress((void**)&cnt_u, g_cnt_u);
    cudaGetSymbolAddress((void**)&off_i, g_off_i);
    cudaGetSymbolAddress((void**)&off_u, g_off_u);
    cudaGetSymbolAddress((void**)&src_i, g_src_i);
    cudaGetSymbolAddress((void**)&src_u, g_src_u);
    cudaGetSymbolAddress((void**)&cur_i, g_cur_i);
    cudaGetSymbolAddress((void**)&cur_u, g_cur_u);
    cudaGetSymbolAddress((void**)&tot_i, g_tot_i);
    cudaGetSymbolAddress((void**)&tot_u, g_tot_u);

    cudaFuncSetAttribute(gemm_mma, cudaFuncAttributeMaxDynamicSharedMemorySize, SMEM_BYTES);

    static Ctx ctx;
    const cudaStream_t L = 0;      // captured legacy stream

    // ---- fork: CSR build runs concurrently with the GEMM ----
    cudaEventRecord(ctx.evFork, L);
    cudaStreamWaitEvent(ctx.s1, ctx.evFork, 0);
    {
        const int nmax = (nU > nI) ? nU : nI;
        zero_k<<<(nmax + 255) / 256, 256, 0, ctx.s1>>>(nI, nU);
        count_k<<<(E + 255) / 256, 256, 0, ctx.s1>>>(edges, edges + E, E);
        alloc_k<<<(nI + 1023) / 1024, 1024, 0, ctx.s1>>>(cnt_i, off_i, cur_i, nI, tot_i);
        alloc_k<<<(nU + 1023) / 1024, 1024, 0, ctx.s1>>>(cnt_u, off_u, cur_u, nU, tot_u);
        fill_k<<<(E + 255) / 256, 256, 0, ctx.s1>>>(edges, edges + E, E);
        cudaEventRecord(ctx.evCSR, ctx.s1);
    }

    // ---- L: single unified GEMM launch (user + item blocks side by side) ----
    int split = (int)((152LL * nU) / (nU + nI));
    if (split < 1) split = 1;
    if (split > 151) split = 151;
    gemm_mma<<<152, GEMM_THREADS, SMEM_BYTES, L>>>(
        user_feat, nU, W_user, b_user, W_u2i, user_out, u2i_ptr,
        item_feat, nI, W_item, b_item, W_i2u, item_out, i2u_ptr,
        split);
    cudaEventRecord(ctx.evG, L);

    // ---- gathers (concurrent on two streams; need GEMM + CSR) ----
    const int wpb = 256 / 32;
    cudaStreamWaitEvent(L, ctx.evCSR, 0);
    gather_k<<<(nI + wpb - 1) / wpb, 256, 0, L>>>(
        off_i, cnt_i, src_i, u2i_ptr, b_u2i, item_out, nI);

    cudaStreamWaitEvent(ctx.s2, ctx.evG, 0);
    cudaStreamWaitEvent(ctx.s2, ctx.evCSR, 0);
    gather_k<<<(nU + wpb - 1) / wpb, 256, 0, ctx.s2>>>(
        off_u, cnt_u, src_u, i2u_ptr, b_i2u, user_out, nU);
    cudaEventRecord(ctx.evS2, ctx.s2);

    // ---- join ----
    cudaStreamWaitEvent(L, ctx.evS2, 0);
}

// round 10
// speedup vs baseline: 1.1845x; 1.1845x over previous
#include <cuda_runtime.h>
#include <cuda_fp16.h>
#include <cstdint>
#include <cstddef>

#define D 128
#define TILE_ROWS 128
#define GEMM_THREADS 512   // 16 warps: wm = wid&3 (32-row quarter), wn = wid>>2 (64-col group)

#define NUM_USERS_MAX 100000
#define NUM_ITEMS_MAX 50000
#define NUM_EDGES_MAX 600000

// Scratch (allocation-free rule: device globals). Messages stored fp16.
__device__ __half g_U2I[NUM_USERS_MAX * 128];
__device__ __half g_I2U[NUM_ITEMS_MAX * 128];

// CSR scratch
__device__ int g_cnt_i[NUM_ITEMS_MAX];
__device__ int g_cnt_u[NUM_USERS_MAX];
__device__ int g_off_i[NUM_ITEMS_MAX];
__device__ int g_off_u[NUM_USERS_MAX];
__device__ int g_cur_i[NUM_ITEMS_MAX];
__device__ int g_cur_u[NUM_USERS_MAX];
__device__ int g_src_i[NUM_EDGES_MAX];
__device__ int g_src_u[NUM_EDGES_MAX];
__device__ int g_tot_i;
__device__ int g_tot_u;

__device__ __forceinline__ float tf32r(float x) {
    float r;
    asm("cvt.rna.tf32.f32 %0, %1;" : "=f"(r) : "f"(x));
    return r;
}

__device__ __forceinline__ void mma_tf32(float* c, const uint32_t* a, uint32_t b0, uint32_t b1) {
    asm volatile(
        "mma.sync.aligned.m16n8k8.row.col.f32.tf32.tf32.f32 "
        "{%0,%1,%2,%3}, {%4,%5,%6,%7}, {%8,%9}, {%0,%1,%2,%3};"
        : "+f"(c[0]), "+f"(c[1]), "+f"(c[2]), "+f"(c[3])
        : "r"(a[0]), "r"(a[1]), "r"(a[2]), "r"(a[3]), "r"(b0), "r"(b1));
}

// smem layout:
//   Wfrag (paired): 16 ksteps x 16 nt-pairs x 32 lanes x uint4 = 131072 B
//     entry (ks, p, lane) = { b0(nt=2p), b1(nt=2p), b0(nt=2p+1), b1(nt=2p+1) }
//     where bj for tile nt: W'(k=ks*8 + t + 4j, o=nt*8+g), g=lane>>2, t=lane&3
//   Xs: 128 rows x 132 floats (pad 4 kills bank conflicts) at 131072 B
#define XS_OFF_F 32768
#define XS_LD    132
#define SMEM_BYTES (131072 + TILE_ROWS * XS_LD * 4)   // 198656

extern __shared__ __align__(16) float smem_f[];

// Unified persistent GEMM: blocks [0, split) -> user matrices, rest -> item.
__global__ __launch_bounds__(GEMM_THREADS, 1)
void gemm_mma(const float* __restrict__ Xu, int nu,
              const float* __restrict__ Wau, const float* __restrict__ bau,
              const float* __restrict__ Wbu,
              float* __restrict__ Yu, __half* __restrict__ Mu,
              const float* __restrict__ Xi, int ni,
              const float* __restrict__ Wai, const float* __restrict__ bai,
              const float* __restrict__ Wbi,
              float* __restrict__ Yi, __half* __restrict__ Mi,
              int split)
{
    uint4* Wfrag = (uint4*)smem_f;
    float* Xs    = smem_f + XS_OFF_F;

    const int tid  = threadIdx.x;
    const int lane = tid & 31;
    const int wid  = tid >> 5;
    const int wm   = wid & 3;        // 32-row quarter of the 128-row tile
    const int wn   = wid >> 2;       // 0..3: 64-col group within 256 outs
    const int g    = lane >> 2;
    const int t    = lane & 3;

    // Per-block work selection
    const float *X, *Wa, *ba, *Wb;
    float* Yself;
    __half* Ymsg;
    int nrows, bidx, nblk;
    if (blockIdx.x < split) {
        X = Xu; Wa = Wau; ba = bau; Wb = Wbu; Yself = Yu; Ymsg = Mu;
        nrows = nu; bidx = blockIdx.x; nblk = split;
    } else {
        X = Xi; Wa = Wai; ba = bai; Wb = Wbi; Yself = Yi; Ymsg = Mi;
        nrows = ni; bidx = blockIdx.x - split; nblk = gridDim.x - split;
    }

    // Build paired W fragments once (tf32-rounded).
    // i enumerates (ks, p, lane); each thread fills one uint4 (two nt fragments).
    for (int i = tid; i < 16 * 16 * 32; i += GEMM_THREADS) {
        const int l  = i & 31;
        const int p  = (i >> 5) & 15;
        const int ks = i >> 9;
        const int gg = l >> 2;
        const int tt = l & 3;
        const int k  = ks * 8 + tt;
        const int o0 = (2 * p) * 8 + gg;
        const int o1 = o0 + 8;
        const float* W0 = (o0 < 128) ? (Wa + (size_t)o0 * 128) : (Wb + (size_t)(o0 - 128) * 128);
        const float* W1 = (o1 < 128) ? (Wa + (size_t)o1 * 128) : (Wb + (size_t)(o1 - 128) * 128);
        uint4 v;
        v.x = __float_as_uint(tf32r(W0[k]));
        v.y = __float_as_uint(tf32r(W0[k + 4]));
        v.z = __float_as_uint(tf32r(W1[k]));
        v.w = __float_as_uint(tf32r(W1[k + 4]));
        Wfrag[i] = v;
    }

    float2 bias2[8];
    if (wn < 2) {
        #pragma unroll
        for (int nt = 0; nt < 8; nt++) {
            const int col = wn * 64 + nt * 8 + t * 2;
            bias2[nt] = make_float2(ba[col], ba[col + 1]);
        }
    }

    const int ntiles = (nrows + TILE_ROWS - 1) / TILE_ROWS;

    for (int tile = bidx; tile < ntiles; tile += nblk) {
        const int row0 = tile * TILE_ROWS;
        __syncthreads();

        for (int i = tid; i < TILE_ROWS * 32; i += GEMM_THREADS) {
            const int r = i >> 5, q = i & 31;
            float4 v = make_float4(0.f, 0.f, 0.f, 0.f);
            if (row0 + r < nrows) {
                v = *(const float4*)&X[(size_t)(row0 + r) * D + q * 4];
                v.x = tf32r(v.x); v.y = tf32r(v.y); v.z = tf32r(v.z); v.w = tf32r(v.w);
            }
            *(float4*)&Xs[r * XS_LD + q * 4] = v;
        }
        __syncthreads();

        float acc[2][8][4];
        #pragma unroll
        for (int mt = 0; mt < 2; mt++)
            #pragma unroll
            for (int nt = 0; nt < 8; nt++)
                #pragma unroll
                for (int j = 0; j < 4; j++) acc[mt][nt][j] = 0.f;

        #pragma unroll
        for (int ks = 0; ks < 16; ks++) {
            const int k0 = ks * 8;
            uint32_t a[2][4];
            #pragma unroll
            for (int mt = 0; mt < 2; mt++) {
                const int row = wm * 32 + mt * 16 + g;
                a[mt][0] = __float_as_uint(Xs[row * XS_LD + k0 + t]);
                a[mt][1] = __float_as_uint(Xs[(row + 8) * XS_LD + k0 + t]);
                a[mt][2] = __float_as_uint(Xs[row * XS_LD + k0 + t + 4]);
                a[mt][3] = __float_as_uint(Xs[(row + 8) * XS_LD + k0 + t + 4]);
            }
            #pragma unroll
            for (int np = 0; np < 4; np++) {
                // pair np covers nt = 2*np, 2*np+1 within this warp's 8-nt group
                const uint4 b = Wfrag[(size_t)(ks * 16 + wn * 4 + np) * 32 + lane];
                const int nt0 = 2 * np, nt1 = 2 * np + 1;
                mma_tf32(acc[0][nt0], a[0], b.x, b.y);
                mma_tf32(acc[1][nt0], a[1], b.x, b.y);
                mma_tf32(acc[0][nt1], a[0], b.z, b.w);
                mma_tf32(acc[1][nt1], a[1], b.z, b.w);
            }
        }

        #pragma unroll
        for (int mt = 0; mt < 2; mt++) {
            const int r0 = row0 + wm * 32 + mt * 16 + g;
            const int r1 = r0 + 8;
            #pragma unroll
            for (int nt = 0; nt < 8; nt++) {
                const int colg = wn * 64 + nt * 8 + t * 2;
                if (wn < 2) {
                    if (r0 < nrows)
                        *(float2*)&Yself[(size_t)r0 * D + colg] =
                            make_float2(acc[mt][nt][0] + bias2[nt].x,
                                        acc[mt][nt][1] + bias2[nt].y);
                    if (r1 < nrows)
                        *(float2*)&Yself[(size_t)r1 * D + colg] =
                            make_float2(acc[mt][nt][2] + bias2[nt].x,
                                        acc[mt][nt][3] + bias2[nt].y);
                } else {
                    const int colm = colg - 128;
                    if (r0 < nrows)
                        *(__half2*)&Ymsg[(size_t)r0 * D + colm] =
                            __floats2half2_rn(acc[mt][nt][0], acc[mt][nt][1]);
                    if (r1 < nrows)
                        *(__half2*)&Ymsg[(size_t)r1 * D + colm] =
                            __floats2half2_rn(acc[mt][nt][2], acc[mt][nt][3]);
                }
            }
        }
    }
}

// ============================ CSR build ============================
__global__ void zero_k(int nI, int nU) {
    const int i = blockIdx.x * blockDim.x + threadIdx.x;
    if (i < nI) g_cnt_i[i] = 0;
    if (i < nU) g_cnt_u[i] = 0;
    if (i == 0) { g_tot_i = 0; g_tot_u = 0; }
}

__global__ void count_k(const int* __restrict__ eu, const int* __restrict__ ei, int E) {
    const int e = blockIdx.x * blockDim.x + threadIdx.x;
    if (e < E) {
        atomicAdd(&g_cnt_i[__ldg(&ei[e])], 1);
        atomicAdd(&g_cnt_u[__ldg(&eu[e])], 1);
    }
}

// Chip-wide segment allocator: block prefix + ONE atomicAdd per block.
__global__ void alloc_k(const int* __restrict__ cnt, int* __restrict__ off,
                        int* __restrict__ cur, int n, int* __restrict__ total)
{
    __shared__ int wtot[32];
    __shared__ int blk_base;
    const int i = blockIdx.x * blockDim.x + threadIdx.x;
    const int lane = threadIdx.x & 31;
    const int wid = threadIdx.x >> 5;
    const int nw = blockDim.x >> 5;

    const int v = (i < n) ? cnt[i] : 0;

    int p = v;
    #pragma unroll
    for (int d = 1; d < 32; d <<= 1) {
        int t = __shfl_up_sync(0xFFFFFFFFu, p, d);
        if (lane >= d) p += t;
    }
    const int warp_excl = p - v;
    if (lane == 31) wtot[wid] = p;
    __syncthreads();

    if (wid == 0) {
        int wv = (lane < nw) ? wtot[lane] : 0;
        int q = wv;
        #pragma unroll
        for (int d = 1; d < 32; d <<= 1) {
            int t = __shfl_up_sync(0xFFFFFFFFu, q, d);
            if (lane >= d) q += t;
        }
        wtot[lane] = q - wv;
        if (lane == nw - 1) blk_base = atomicAdd(total, q);
    }
    __syncthreads();

    if (i < n) {
        const int o = blk_base + wtot[wid] + warp_excl;
        off[i] = o;
        cur[i] = o;
    }
}

__global__ void fill_k(const int* __restrict__ eu, const int* __restrict__ ei, int E) {
    const int e = blockIdx.x * blockDim.x + threadIdx.x;
    if (e < E) {
        const int u  = __ldg(&eu[e]);
        const int it = __ldg(&ei[e]);
        const int p = atomicAdd(&g_cur_i[it], 1);
        g_src_i[p] = u;
        const int q = atomicAdd(&g_cur_u[u], 1);
        g_src_u[q] = it;
    }
}

// ============================ Gather (fp16 messages) ============================
__device__ __forceinline__ void acc_half4(float4& acc, uint2 raw) {
    const __half2 h0 = *(__half2*)&raw.x;
    const __half2 h1 = *(__half2*)&raw.y;
    const float2 f0 = __half22float2(h0);
    const float2 f1 = __half22float2(h1);
    acc.x += f0.x; acc.y += f0.y; acc.z += f1.x; acc.w += f1.y;
}

__global__ void gather_k(const int* __restrict__ off, const int* __restrict__ cnt,
                         const int* __restrict__ src, const __half* __restrict__ msgs,
                         const float* __restrict__ bias, float* __restrict__ out, int n)
{
    const int node = (blockIdx.x * blockDim.x + threadIdx.x) >> 5;
    if (node >= n) return;
    const int lane = threadIdx.x & 31;
    const int offc = lane * 4;
    const int base = __ldg(&off[node]);
    const int deg  = __ldg(&cnt[node]);

    float4 acc = make_float4(0.f, 0.f, 0.f, 0.f);
    int j = 0;
    for (; j + 4 <= deg; j += 4) {
        const int s0 = __ldg(&src[base + j]);
        const int s1 = __ldg(&src[base + j + 1]);
        const int s2 = __ldg(&src[base + j + 2]);
        const int s3 = __ldg(&src[base + j + 3]);
        const uint2 r0 = *(const uint2*)&msgs[(size_t)s0 * D + offc];
        const uint2 r1 = *(const uint2*)&msgs[(size_t)s1 * D + offc];
        const uint2 r2 = *(const uint2*)&msgs[(size_t)s2 * D + offc];
        const uint2 r3 = *(const uint2*)&msgs[(size_t)s3 * D + offc];
        acc_half4(acc, r0); acc_half4(acc, r1);
        acc_half4(acc, r2); acc_half4(acc, r3);
    }
    for (; j < deg; j++) {
        const int s = __ldg(&src[base + j]);
        acc_half4(acc, *(const uint2*)&msgs[(size_t)s * D + offc]);
    }

    const float fd = (float)deg;
    const float4 b = *(const float4*)&bias[offc];
    float4* po = (float4*)&out[(size_t)node * D + offc];
    float4 o = *po;
    o.x += acc.x + fd * b.x;
    o.y += acc.y + fd * b.y;
    o.z += acc.z + fd * b.z;
    o.w += acc.w + fd * b.w;
    *po = o;
}

// ============================ Host ============================
struct Ctx {
    cudaStream_t s1, s2;
    cudaEvent_t evFork, evCSR, evG, evS2;
    Ctx() {
        cudaStreamCreateWithFlags(&s1, cudaStreamNonBlocking);
        cudaStreamCreateWithFlags(&s2, cudaStreamNonBlocking);
        cudaEventCreateWithFlags(&evFork, cudaEventDisableTiming);
        cudaEventCreateWithFlags(&evCSR,  cudaEventDisableTiming);
        cudaEventCreateWithFlags(&evG,    cudaEventDisableTiming);
        cudaEventCreateWithFlags(&evS2,   cudaEventDisableTiming);
    }
};

extern "C" void kernel_launch(void* const* d_in, const int* in_sizes, int n_in,
                              void* d_out, int out_size)
{
    const float* user_feat = (const float*)d_in[0];
    const float* item_feat = (const float*)d_in[1];
    const int*   edges     = (const int*)d_in[2];
    const float* W_user = (const float*)d_in[3];
    const float* b_user = (const float*)d_in[4];
    const float* W_item = (const float*)d_in[5];
    const float* b_item = (const float*)d_in[6];
    const float* W_u2i  = (const float*)d_in[7];
    const float* b_u2i  = (const float*)d_in[8];
    const float* W_i2u  = (const float*)d_in[9];
    const float* b_i2u  = (const float*)d_in[10];

    const int nU = in_sizes[0] / D;
    const int nI = in_sizes[1] / D;
    const int E  = in_sizes[2] / 2;

    float* user_out = (float*)d_out;
    float* item_out = (float*)d_out + (size_t)nU * D;

    __half *u2i_ptr, *i2u_ptr;
    cudaGetSymbolAddress((void**)&u2i_ptr, g_U2I);
    cudaGetSymbolAddress((void**)&i2u_ptr, g_I2U);
    int *cnt_i, *cnt_u, *off_i, *off_u, *src_i, *src_u, *cur_i, *cur_u, *tot_i, *tot_u;
    cudaGetSymbolAddress((void**)&cnt_i, g_cnt_i);
    cudaGetSymbolAddress((void**)&cnt_u, g_cnt_u);
    cudaGetSymbolAddress((void**)&off_i, g_off_i);
    cudaGetSymbolAddress((void**)&off_u, g_off_u);
    cudaGetSymbolAddress((void**)&src_i, g_src_i);
    cudaGetSymbolAddress((void**)&src_u, g_src_u);
    cudaGetSymbolAddress((void**)&cur_i, g_cur_i);
    cudaGetSymbolAddress((void**)&cur_u, g_cur_u);
    cudaGetSymbolAddress((void**)&tot_i, g_tot_i);
    cudaGetSymbolAddress((void**)&tot_u, g_tot_u);

    cudaFuncSetAttribute(gemm_mma, cudaFuncAttributeMaxDynamicSharedMemorySize, SMEM_BYTES);

    static Ctx ctx;
    const cudaStream_t L = 0;      // captured legacy stream

    // ---- fork: CSR build runs concurrently with the GEMM ----
    cudaEventRecord(ctx.evFork, L);
    cudaStreamWaitEvent(ctx.s1, ctx.evFork, 0);
    {
        const int nmax = (nU > nI) ? nU : nI;
        zero_k<<<(nmax + 255) / 256, 256, 0, ctx.s1>>>(nI, nU);
        count_k<<<(E + 255) / 256, 256, 0, ctx.s1>>>(edges, edges + E, E);
        alloc_k<<<(nI + 1023) / 1024, 1024, 0, ctx.s1>>>(cnt_i, off_i, cur_i, nI, tot_i);
        alloc_k<<<(nU + 1023) / 1024, 1024, 0, ctx.s1>>>(cnt_u, off_u, cur_u, nU, tot_u);
        fill_k<<<(E + 255) / 256, 256, 0, ctx.s1>>>(edges, edges + E, E);
        cudaEventRecord(ctx.evCSR, ctx.s1);
    }

    // ---- L: single unified GEMM launch (user + item blocks side by side) ----
    int split = (int)((152LL * nU) / (nU + nI));
    if (split < 1) split = 1;
    if (split > 151) split = 151;
    gemm_mma<<<152, GEMM_THREADS, SMEM_BYTES, L>>>(
        user_feat, nU, W_user, b_user, W_u2i, user_out, u2i_ptr,
        item_feat, nI, W_item, b_item, W_i2u, item_out, i2u_ptr,
        split);
    cudaEventRecord(ctx.evG, L);

    // ---- gathers (concurrent on two streams; need GEMM + CSR) ----
    const int wpb = 256 / 32;
    cudaStreamWaitEvent(L, ctx.evCSR, 0);
    gather_k<<<(nI + wpb - 1) / wpb, 256, 0, L>>>(
        off_i, cnt_i, src_i, u2i_ptr, b_u2i, item_out, nI);

    cudaStreamWaitEvent(ctx.s2, ctx.evG, 0);
    cudaStreamWaitEvent(ctx.s2, ctx.evCSR, 0);
    gather_k<<<(nU + wpb - 1) / wpb, 256, 0, ctx.s2>>>(
        off_u, cnt_u, src_u, i2u_ptr, b_i2u, user_out, nU);
    cudaEventRecord(ctx.evS2, ctx.s2);

    // ---- join ----
    cudaStreamWaitEvent(L, ctx.evS2, 0);
}